// round 11
// baseline (speedup 1.0000x reference)
#include <cuda_runtime.h>
#include <cstdint>

// Problem constants
static constexpr int B = 2, N = 4, D = 48, H = 28, W = 60, C = 64;
static constexpr int DOWNSAMPLE = 8;
static constexpr int NX = 192, NY = 192, NZ = 1;
static constexpr float F_BEV = 4.0f;           // 1/SCALE
static constexpr float CX_BEV = 96.0f;         // NX/2 + OFFSETX
static constexpr float CY_BEV = 96.0f;         // NY/2
static constexpr float DMIN = 2.0f, DSTEP = 1.0f;

static constexpr int NCOL  = B * N * D * W;    // 23040 columns (b,n,d,w)
static constexpr int PLANE = NY * NX;          // 36864
static constexpr int OUT_ELEMS = B * NZ * C * PLANE;  // 4,718,592 floats
static constexpr int OUT_F4   = OUT_ELEMS / 4;        // 1,179,648 float4

// ---------------------------------------------------------------------------
// d_out zeroing (output is the accumulator). Grid-stride float4 loop.
// ---------------------------------------------------------------------------
__global__ void fp_zero(float* __restrict__ out) {
    float4* o4 = reinterpret_cast<float4*>(out);
    const float4 z = make_float4(0.f, 0.f, 0.f, 0.f);
    for (int i = blockIdx.x * blockDim.x + threadIdx.x; i < OUT_F4;
         i += gridDim.x * blockDim.x) {
        o4[i] = z;
    }
}

// ---------------------------------------------------------------------------
// Per-(b,n) geometry precompute into shared memory: combine = R @ inv(K),
// plus translation. Called by the first BN threads of each block.
// ---------------------------------------------------------------------------
__device__ __forceinline__ void fp_setup_geom(int i,
                                              const float* __restrict__ intr,
                                              const float* __restrict__ pose,
                                              float* __restrict__ s_geom) {
    const float* K = intr + i * 9;
    float a = K[0], b = K[1], c = K[2];
    float d = K[3], e = K[4], f = K[5];
    float g = K[6], h = K[7], ii = K[8];
    float A  = e * ii - f * h;
    float Bc = f * g - d * ii;
    float Cc = d * h - e * g;
    float inv_det = 1.0f / (a * A + b * Bc + c * Cc);
    float inv[9];
    inv[0] = A * inv_det;  inv[1] = (c * h - b * ii) * inv_det; inv[2] = (b * f - c * e) * inv_det;
    inv[3] = Bc * inv_det; inv[4] = (a * ii - c * g) * inv_det; inv[5] = (c * d - a * f) * inv_det;
    inv[6] = Cc * inv_det; inv[7] = (b * g - a * h) * inv_det;  inv[8] = (a * e - b * d) * inv_det;
    const float* P = pose + i * 16;
    for (int r = 0; r < 3; r++) {
        for (int cc = 0; cc < 3; cc++) {
            float s = 0.f;
            for (int k = 0; k < 3; k++) s += P[r * 4 + k] * inv[k * 3 + cc];
            s_geom[i * 12 + r * 3 + cc] = s;
        }
        s_geom[i * 12 + 9 + r] = P[r * 4 + 3];
    }
}

// ---------------------------------------------------------------------------
// Scatter directly into out (B, C, NY, NX).
// Warp = ONE column (b,n,d,w). lane = seg*16 + q (seg in {0,1}, q = quad).
// Phase 1: lane evaluates voxel(col, h=lane) for lane<28 into a per-warp
//          smem table; ballot -> 28-bit kept mask.
// Phase 2: lane streams its segment's kept interval (<=14 h) with
//          unconditional float4 loads; voxel via LDS broadcast; run-length
//          accumulate; flush = 4 scalar red.add.f32 (channel-strided).
// ---------------------------------------------------------------------------
__global__ __launch_bounds__(256) void fp_scatter(
        const float* __restrict__ x,
        const float* __restrict__ intr,
        const float* __restrict__ pose,
        float* __restrict__ out) {
    __shared__ float s_geom[B * N * 12];
    __shared__ int s_vox[8][28];                 // per-warp voxel table

    if (threadIdx.x < B * N) fp_setup_geom(threadIdx.x, intr, pose, s_geom);
    __syncthreads();

    const int gtid = blockIdx.x * 256 + threadIdx.x;   // 0 .. NCOL*32-1 (exact)
    const int lane = threadIdx.x & 31;
    const int wid  = threadIdx.x >> 5;                 // warp in block
    const int q    = lane & 15;
    const int seg  = lane >> 4;                        // 0: h<14, 1: h>=14
    const int cid  = gtid >> 5;                        // column (b,n,d,w)

    // decode column:  cid = ((b*N+n)*D + d)*W + w
    const int w   = cid % W;
    const int bnd = cid / W;              // (b*N+n)*D + d
    const int dd  = bnd % D;
    const int bn  = bnd / D;              // b*N + n
    const int b   = bn >> 2;              // /N

    const float* cm = s_geom + bn * 12;
    const float cm0 = cm[0], cm1 = cm[1], cm2 = cm[2], cm9  = cm[9];
    const float cm3 = cm[3], cm4 = cm[4], cm5 = cm[5], cm10 = cm[10];
    const float cm6 = cm[6], cm7 = cm[7], cm8 = cm[8], cm11 = cm[11];

    const float STEPX = (float)(W * DOWNSAMPLE - 1) / (float)(W - 1);
    const float STEPY = (float)(H * DOWNSAMPLE - 1) / (float)(H - 1);
    const float dep = DMIN + (float)dd * DSTEP;
    const float px  = ((float)w * STEPX) * dep;
    const float pz  = dep;

    // --- Phase 1: lane evaluates geometry for h = lane (lane < 28) ---
    // identical fmaf chains to the verified kernels (bin-boundary stability)
    int veval = -1;
    if (lane < H) {
        float v  = (float)lane * STEPY;
        float py = v * dep;
        float gxf = fmaf(cm0, px, fmaf(cm1, py, fmaf(cm2, pz, cm9)));
        float gyf = fmaf(cm3, px, fmaf(cm4, py, fmaf(cm5, pz, cm10)));
        float gzf = fmaf(cm6, px, fmaf(cm7, py, fmaf(cm8, pz, cm11)));
        int gx = (int)(gxf * F_BEV + CX_BEV);     // trunc == astype(int32)
        int gy = (int)(gyf * F_BEV + CY_BEV);
        int gz = (int)((gzf + 10.0f) / 20.0f);
        bool kept = (gx >= 0) & (gx < NX) & (gy >= 0) & (gy < NY) & (gz >= 0) & (gz < NZ);
        if (kept) veval = (gz * NY + gy) * NX + gx;   // NZ=1 -> plane index
    }
    if (lane < H) s_vox[wid][lane] = veval;
    unsigned mask = __ballot_sync(0xffffffffu, veval >= 0);  // bits 0..27
    __syncwarp();
    if (mask == 0u) return;                   // whole column dead (warp exit)

    // --- this lane's segment interval ---
    const int base = seg * 14;
    unsigned m = (mask >> base) & 0x3FFFu;    // 14 bits
    if (m == 0u) return;                      // this half-column keeps nothing
    const int hmin = base + (__ffs(m) - 1);
    const int hmax = base + (31 - __clz(m));

    // --- Phase 2: data loop, unconditional loads over kept interval ---
    const float* xp = x + ((size_t)(bnd * H + hmin) * W + w) * C + q * 4;
    float* const outbase = out + ((size_t)b * C + q * 4) * PLANE;
    const int* const vt = s_vox[wid];

    int curv = -1;
    float4 acc = make_float4(0.f, 0.f, 0.f, 0.f);

    #pragma unroll 4
    for (int h = hmin; h <= hmax; h++) {
        const float4 val = *reinterpret_cast<const float4*>(xp);
        const int vox = vt[h];                 // LDS broadcast across 16 q-lanes
        if (vox >= 0) {
            if (vox == curv) {
                acc.x += val.x; acc.y += val.y; acc.z += val.z; acc.w += val.w;
            } else {
                if (curv >= 0) {
                    float* dst = outbase + curv;
                    asm volatile("red.global.add.f32 [%0], %1;" :: "l"(dst),             "f"(acc.x) : "memory");
                    asm volatile("red.global.add.f32 [%0], %1;" :: "l"(dst + PLANE),     "f"(acc.y) : "memory");
                    asm volatile("red.global.add.f32 [%0], %1;" :: "l"(dst + 2 * PLANE), "f"(acc.z) : "memory");
                    asm volatile("red.global.add.f32 [%0], %1;" :: "l"(dst + 3 * PLANE), "f"(acc.w) : "memory");
                }
                curv = vox;
                acc = val;
            }
        }
        xp += W * C;
    }
    if (curv >= 0) {
        float* dst = outbase + curv;
        asm volatile("red.global.add.f32 [%0], %1;" :: "l"(dst),             "f"(acc.x) : "memory");
        asm volatile("red.global.add.f32 [%0], %1;" :: "l"(dst + PLANE),     "f"(acc.y) : "memory");
        asm volatile("red.global.add.f32 [%0], %1;" :: "l"(dst + 2 * PLANE), "f"(acc.z) : "memory");
        asm volatile("red.global.add.f32 [%0], %1;" :: "l"(dst + 3 * PLANE), "f"(acc.w) : "memory");
    }
}

// ---------------------------------------------------------------------------
extern "C" void kernel_launch(void* const* d_in, const int* in_sizes, int n_in,
                              void* d_out, int out_size) {
    const float* x    = (const float*)d_in[0];
    const float* intr = (const float*)d_in[1];
    const float* pose = (const float*)d_in[2];
    float* out = (float*)d_out;

    // grid-stride: covers all OUT_F4 float4
    fp_zero<<<1184, 256>>>(out);

    // NCOL*32 = 737,280 threads = 2880 blocks x 256 (exact)
    fp_scatter<<<2880, 256>>>(x, intr, pose, out);
}

// round 12
// speedup vs baseline: 1.0906x; 1.0906x over previous
#include <cuda_runtime.h>
#include <cstdint>

// Problem constants
static constexpr int B = 2, N = 4, D = 48, H = 28, W = 60, C = 64;
static constexpr int DOWNSAMPLE = 8;
static constexpr int NX = 192, NY = 192, NZ = 1;
static constexpr float F_BEV = 4.0f;           // 1/SCALE
static constexpr float CX_BEV = 96.0f;         // NX/2 + OFFSETX
static constexpr float CY_BEV = 96.0f;         // NY/2
static constexpr float DMIN = 2.0f, DSTEP = 1.0f;

static constexpr int NCOL  = B * N * D * W;    // 23040 columns (b,n,d,w)
static constexpr int PLANE = NY * NX;          // 36864
static constexpr int OUT_ELEMS = B * NZ * C * PLANE;  // 4,718,592 floats
static constexpr int OUT_F4   = OUT_ELEMS / 4;        // 1,179,648 float4

// Scalar f32 atomic add WITHOUT a "memory" clobber: volatile keeps it alive
// and ordered vs other volatile asm, but lets the compiler hoist independent
// x-loads across it (the clobber was serializing the whole load stream).
#define RED_ADD_F32(ptr, v) \
    asm volatile("red.global.add.f32 [%0], %1;" :: "l"(ptr), "f"(v))

// ---------------------------------------------------------------------------
// d_out zeroing (output is the accumulator). Grid-stride float4 loop.
// ---------------------------------------------------------------------------
__global__ void fp_zero(float* __restrict__ out) {
    float4* o4 = reinterpret_cast<float4*>(out);
    const float4 z = make_float4(0.f, 0.f, 0.f, 0.f);
    for (int i = blockIdx.x * blockDim.x + threadIdx.x; i < OUT_F4;
         i += gridDim.x * blockDim.x) {
        o4[i] = z;
    }
}

// ---------------------------------------------------------------------------
// Per-(b,n) geometry precompute into shared memory: combine = R @ inv(K) + t.
// ---------------------------------------------------------------------------
__device__ __forceinline__ void fp_setup_geom(int i,
                                              const float* __restrict__ intr,
                                              const float* __restrict__ pose,
                                              float* __restrict__ s_geom) {
    const float* K = intr + i * 9;
    float a = K[0], b = K[1], c = K[2];
    float d = K[3], e = K[4], f = K[5];
    float g = K[6], h = K[7], ii = K[8];
    float A  = e * ii - f * h;
    float Bc = f * g - d * ii;
    float Cc = d * h - e * g;
    float inv_det = 1.0f / (a * A + b * Bc + c * Cc);
    float inv[9];
    inv[0] = A * inv_det;  inv[1] = (c * h - b * ii) * inv_det; inv[2] = (b * f - c * e) * inv_det;
    inv[3] = Bc * inv_det; inv[4] = (a * ii - c * g) * inv_det; inv[5] = (c * d - a * f) * inv_det;
    inv[6] = Cc * inv_det; inv[7] = (b * g - a * h) * inv_det;  inv[8] = (a * e - b * d) * inv_det;
    const float* P = pose + i * 16;
    for (int r = 0; r < 3; r++) {
        for (int cc = 0; cc < 3; cc++) {
            float s = 0.f;
            for (int k = 0; k < 3; k++) s += P[r * 4 + k] * inv[k * 3 + cc];
            s_geom[i * 12 + r * 3 + cc] = s;
        }
        s_geom[i * 12 + 9 + r] = P[r * 4 + 3];
    }
}

// ---------------------------------------------------------------------------
// Scatter directly into out (B, C, NY, NX).
// Warp = ONE column (b,n,d,w). lane = seg*16 + q (seg in {0,1}, q = quad).
// Phase 1: lane evaluates voxel(col, h=lane) for lane<28 into a per-warp
//          smem table; ballot -> 28-bit kept mask; per-segment kept span.
// Phase 2: fixed-trip fully-unrolled 14-iteration loop; loads are
//          UNCONDITIONAL with span-clamped addresses (branch-free load
//          stream, no clobber barrier -> ptxas batches them, MLP 4-8);
//          accumulate predicated by mask bit; run-length flush via
//          channel-strided scalar red.add.f32.
// ---------------------------------------------------------------------------
__global__ __launch_bounds__(256) void fp_scatter(
        const float* __restrict__ x,
        const float* __restrict__ intr,
        const float* __restrict__ pose,
        float* __restrict__ out) {
    __shared__ float s_geom[B * N * 12];
    __shared__ int s_vox[8][28];                 // per-warp voxel table

    if (threadIdx.x < B * N) fp_setup_geom(threadIdx.x, intr, pose, s_geom);
    __syncthreads();

    const int gtid = blockIdx.x * 256 + threadIdx.x;   // 0 .. NCOL*32-1 (exact)
    const int lane = threadIdx.x & 31;
    const int wid  = threadIdx.x >> 5;                 // warp in block
    const int q    = lane & 15;
    const int seg  = lane >> 4;                        // 0: h<14, 1: h>=14
    const int cid  = gtid >> 5;                        // column (b,n,d,w)

    // decode column:  cid = ((b*N+n)*D + d)*W + w
    const int w   = cid % W;
    const int bnd = cid / W;              // (b*N+n)*D + d
    const int dd  = bnd % D;
    const int bn  = bnd / D;              // b*N + n
    const int b   = bn >> 2;              // /N

    const float* cm = s_geom + bn * 12;
    const float cm0 = cm[0], cm1 = cm[1], cm2 = cm[2], cm9  = cm[9];
    const float cm3 = cm[3], cm4 = cm[4], cm5 = cm[5], cm10 = cm[10];
    const float cm6 = cm[6], cm7 = cm[7], cm8 = cm[8], cm11 = cm[11];

    const float STEPX = (float)(W * DOWNSAMPLE - 1) / (float)(W - 1);
    const float STEPY = (float)(H * DOWNSAMPLE - 1) / (float)(H - 1);
    const float dep = DMIN + (float)dd * DSTEP;
    const float px  = ((float)w * STEPX) * dep;
    const float pz  = dep;

    // --- Phase 1: lane evaluates geometry for h = lane (lane < 28) ---
    // identical fmaf chains to the verified kernels (bin-boundary stability)
    int veval = -1;
    if (lane < H) {
        float v  = (float)lane * STEPY;
        float py = v * dep;
        float gxf = fmaf(cm0, px, fmaf(cm1, py, fmaf(cm2, pz, cm9)));
        float gyf = fmaf(cm3, px, fmaf(cm4, py, fmaf(cm5, pz, cm10)));
        float gzf = fmaf(cm6, px, fmaf(cm7, py, fmaf(cm8, pz, cm11)));
        int gx = (int)(gxf * F_BEV + CX_BEV);     // trunc == astype(int32)
        int gy = (int)(gyf * F_BEV + CY_BEV);
        int gz = (int)((gzf + 10.0f) / 20.0f);
        bool kept = (gx >= 0) & (gx < NX) & (gy >= 0) & (gy < NY) & (gz >= 0) & (gz < NZ);
        if (kept) veval = (gz * NY + gy) * NX + gx;   // NZ=1 -> plane index
    }
    if (lane < H) s_vox[wid][lane] = veval;
    unsigned mask = __ballot_sync(0xffffffffu, veval >= 0);  // bits 0..27
    __syncwarp();
    if (mask == 0u) return;                   // whole column dead (warp exit)

    // --- this lane's segment kept span ---
    const int base = seg * 14;
    unsigned m = (mask >> base) & 0x3FFFu;    // 14 bits
    if (m == 0u) return;                      // this half-column keeps nothing
    const int hmin = base + (__ffs(m) - 1);
    const int span = (31 - __clz(m)) - (__ffs(m) - 1);   // 0..13

    // --- Phase 2: fixed-trip loop, branch-free clamped loads ---
    const float* xp0 = x + ((size_t)(bnd * H + hmin) * W + w) * C + q * 4;
    float* const outbase = out + ((size_t)b * C + q * 4) * PLANE;
    const int* const vt = s_vox[wid];
    const size_t hstride = (size_t)W * C;

    int curv = -1;
    float4 acc = make_float4(0.f, 0.f, 0.f, 0.f);

    #pragma unroll
    for (int j = 0; j < 14; j++) {
        const int jc = (j <= span) ? j : span;   // clamp -> always-valid address
        const float4 val = *reinterpret_cast<const float4*>(xp0 + (size_t)jc * hstride);
        const int h = hmin + j;
        const bool live = (j <= span) && ((mask >> h) & 1u);
        if (live) {
            const int vox = vt[h];               // LDS broadcast across q-lanes
            if (vox == curv) {
                acc.x += val.x; acc.y += val.y; acc.z += val.z; acc.w += val.w;
            } else {
                if (curv >= 0) {
                    float* dst = outbase + curv;
                    RED_ADD_F32(dst,             acc.x);
                    RED_ADD_F32(dst + PLANE,     acc.y);
                    RED_ADD_F32(dst + 2 * PLANE, acc.z);
                    RED_ADD_F32(dst + 3 * PLANE, acc.w);
                }
                curv = vox;
                acc = val;
            }
        }
    }
    if (curv >= 0) {
        float* dst = outbase + curv;
        RED_ADD_F32(dst,             acc.x);
        RED_ADD_F32(dst + PLANE,     acc.y);
        RED_ADD_F32(dst + 2 * PLANE, acc.z);
        RED_ADD_F32(dst + 3 * PLANE, acc.w);
    }
}

// ---------------------------------------------------------------------------
extern "C" void kernel_launch(void* const* d_in, const int* in_sizes, int n_in,
                              void* d_out, int out_size) {
    const float* x    = (const float*)d_in[0];
    const float* intr = (const float*)d_in[1];
    const float* pose = (const float*)d_in[2];
    float* out = (float*)d_out;

    // grid-stride: covers all OUT_F4 float4
    fp_zero<<<1184, 256>>>(out);

    // NCOL*32 = 737,280 threads = 2880 blocks x 256 (exact)
    fp_scatter<<<2880, 256>>>(x, intr, pose, out);
}

// round 13
// speedup vs baseline: 1.1104x; 1.0182x over previous
#include <cuda_runtime.h>
#include <cstdint>

// Problem constants
static constexpr int B = 2, N = 4, D = 48, H = 28, W = 60, C = 64;
static constexpr int DOWNSAMPLE = 8;
static constexpr int NX = 192, NY = 192, NZ = 1;
static constexpr float F_BEV = 4.0f;           // 1/SCALE
static constexpr float CX_BEV = 96.0f;         // NX/2 + OFFSETX
static constexpr float CY_BEV = 96.0f;         // NY/2
static constexpr float DMIN = 2.0f, DSTEP = 1.0f;

static constexpr int NCOL  = B * N * D * W;    // 23040 columns (b,n,d,w)
static constexpr int PLANE = NY * NX;          // 36864
static constexpr int OUT_ELEMS = B * NZ * C * PLANE;  // 4,718,592 floats
static constexpr int OUT_F4   = OUT_ELEMS / 4;        // 1,179,648 float4

// Scalar f32 atomic add, no "memory" clobber (would serialize the load stream)
#define RED_ADD_F32(ptr, v) \
    asm volatile("red.global.add.f32 [%0], %1;" :: "l"(ptr), "f"(v))

// ---------------------------------------------------------------------------
// d_out zeroing (output is the accumulator). Grid-stride float4 loop.
// ---------------------------------------------------------------------------
__global__ void fp_zero(float* __restrict__ out) {
    float4* o4 = reinterpret_cast<float4*>(out);
    const float4 z = make_float4(0.f, 0.f, 0.f, 0.f);
    for (int i = blockIdx.x * blockDim.x + threadIdx.x; i < OUT_F4;
         i += gridDim.x * blockDim.x) {
        o4[i] = z;
    }
}

// ---------------------------------------------------------------------------
// Per-(b,n) geometry precompute into shared memory: combine = R @ inv(K) + t.
// ---------------------------------------------------------------------------
__device__ __forceinline__ void fp_setup_geom(int i,
                                              const float* __restrict__ intr,
                                              const float* __restrict__ pose,
                                              float* __restrict__ s_geom) {
    const float* K = intr + i * 9;
    float a = K[0], b = K[1], c = K[2];
    float d = K[3], e = K[4], f = K[5];
    float g = K[6], h = K[7], ii = K[8];
    float A  = e * ii - f * h;
    float Bc = f * g - d * ii;
    float Cc = d * h - e * g;
    float inv_det = 1.0f / (a * A + b * Bc + c * Cc);
    float inv[9];
    inv[0] = A * inv_det;  inv[1] = (c * h - b * ii) * inv_det; inv[2] = (b * f - c * e) * inv_det;
    inv[3] = Bc * inv_det; inv[4] = (a * ii - c * g) * inv_det; inv[5] = (c * d - a * f) * inv_det;
    inv[6] = Cc * inv_det; inv[7] = (b * g - a * h) * inv_det;  inv[8] = (a * e - b * d) * inv_det;
    const float* P = pose + i * 16;
    for (int r = 0; r < 3; r++) {
        for (int cc = 0; cc < 3; cc++) {
            float s = 0.f;
            for (int k = 0; k < 3; k++) s += P[r * 4 + k] * inv[k * 3 + cc];
            s_geom[i * 12 + r * 3 + cc] = s;
        }
        s_geom[i * 12 + 9 + r] = P[r * 4 + 3];
    }
}

// ---------------------------------------------------------------------------
// Scatter directly into out (B, C, NY, NX).
// Warp = ONE column (b,n,d,w). lane = seg*16 + q (seg in {0,1}, q = quad).
// Phase 1: lane evaluates voxel(col, h=lane) for lane<28 into a per-warp
//          smem table; ballot -> 28-bit kept mask; per-segment kept span.
// Phase 2: PRELOAD all 14 float4 into a register array (forces MLP=14 and
//          ~90 regs -- R8/R11/R12 proved ptxas's regs=32 choice caps MLP at
//          ~2 and leaves DRAM at 34%), then run-length accumulate + flush.
// ---------------------------------------------------------------------------
__global__ __launch_bounds__(256) void fp_scatter(
        const float* __restrict__ x,
        const float* __restrict__ intr,
        const float* __restrict__ pose,
        float* __restrict__ out) {
    __shared__ float s_geom[B * N * 12];
    __shared__ int s_vox[8][28];                 // per-warp voxel table

    if (threadIdx.x < B * N) fp_setup_geom(threadIdx.x, intr, pose, s_geom);
    __syncthreads();

    const int gtid = blockIdx.x * 256 + threadIdx.x;   // 0 .. NCOL*32-1 (exact)
    const int lane = threadIdx.x & 31;
    const int wid  = threadIdx.x >> 5;                 // warp in block
    const int q    = lane & 15;
    const int seg  = lane >> 4;                        // 0: h<14, 1: h>=14
    const int cid  = gtid >> 5;                        // column (b,n,d,w)

    // decode column:  cid = ((b*N+n)*D + d)*W + w
    const int w   = cid % W;
    const int bnd = cid / W;              // (b*N+n)*D + d
    const int dd  = bnd % D;
    const int bn  = bnd / D;              // b*N + n
    const int b   = bn >> 2;              // /N

    const float* cm = s_geom + bn * 12;
    const float cm0 = cm[0], cm1 = cm[1], cm2 = cm[2], cm9  = cm[9];
    const float cm3 = cm[3], cm4 = cm[4], cm5 = cm[5], cm10 = cm[10];
    const float cm6 = cm[6], cm7 = cm[7], cm8 = cm[8], cm11 = cm[11];

    const float STEPX = (float)(W * DOWNSAMPLE - 1) / (float)(W - 1);
    const float STEPY = (float)(H * DOWNSAMPLE - 1) / (float)(H - 1);
    const float dep = DMIN + (float)dd * DSTEP;
    const float px  = ((float)w * STEPX) * dep;
    const float pz  = dep;

    // --- Phase 1: lane evaluates geometry for h = lane (lane < 28) ---
    // identical fmaf chains to the verified kernels (bin-boundary stability)
    int veval = -1;
    if (lane < H) {
        float v  = (float)lane * STEPY;
        float py = v * dep;
        float gxf = fmaf(cm0, px, fmaf(cm1, py, fmaf(cm2, pz, cm9)));
        float gyf = fmaf(cm3, px, fmaf(cm4, py, fmaf(cm5, pz, cm10)));
        float gzf = fmaf(cm6, px, fmaf(cm7, py, fmaf(cm8, pz, cm11)));
        int gx = (int)(gxf * F_BEV + CX_BEV);     // trunc == astype(int32)
        int gy = (int)(gyf * F_BEV + CY_BEV);
        int gz = (int)((gzf + 10.0f) / 20.0f);
        bool kept = (gx >= 0) & (gx < NX) & (gy >= 0) & (gy < NY) & (gz >= 0) & (gz < NZ);
        if (kept) veval = (gz * NY + gy) * NX + gx;   // NZ=1 -> plane index
    }
    if (lane < H) s_vox[wid][lane] = veval;
    unsigned mask = __ballot_sync(0xffffffffu, veval >= 0);  // bits 0..27
    __syncwarp();
    if (mask == 0u) return;                   // whole column dead (warp exit)

    // --- this lane's segment kept span ---
    const int base = seg * 14;
    unsigned m = (mask >> base) & 0x3FFFu;    // 14 bits
    if (m == 0u) return;                      // this half-column keeps nothing
    const int hmin = base + (__ffs(m) - 1);
    const int span = (31 - __clz(m)) - (__ffs(m) - 1);   // 0..13

    // --- Phase 2a: PRELOAD all 14 float4 (clamped addresses) into registers.
    // No consumer between loads -> ptxas front-batches all 14 LDGs (MLP=14).
    const float* xp0 = x + ((size_t)(bnd * H + hmin) * W + w) * C + q * 4;
    const size_t hstride = (size_t)W * C;

    float4 vals[14];
    #pragma unroll
    for (int j = 0; j < 14; j++) {
        const int jc = (j <= span) ? j : span;   // clamp -> always-valid address
        vals[j] = *reinterpret_cast<const float4*>(xp0 + (size_t)jc * hstride);
    }

    // --- Phase 2b: run-length accumulate + flush ---
    float* const outbase = out + ((size_t)b * C + q * 4) * PLANE;
    const int* const vt = s_vox[wid];

    int curv = -1;
    float4 acc = make_float4(0.f, 0.f, 0.f, 0.f);

    #pragma unroll
    for (int j = 0; j < 14; j++) {
        const int h = hmin + j;
        const bool live = (j <= span) && ((mask >> h) & 1u);
        if (live) {
            const int vox = vt[h];               // LDS broadcast across q-lanes
            const float4 val = vals[j];
            if (vox == curv) {
                acc.x += val.x; acc.y += val.y; acc.z += val.z; acc.w += val.w;
            } else {
                if (curv >= 0) {
                    float* dst = outbase + curv;
                    RED_ADD_F32(dst,             acc.x);
                    RED_ADD_F32(dst + PLANE,     acc.y);
                    RED_ADD_F32(dst + 2 * PLANE, acc.z);
                    RED_ADD_F32(dst + 3 * PLANE, acc.w);
                }
                curv = vox;
                acc = val;
            }
        }
    }
    if (curv >= 0) {
        float* dst = outbase + curv;
        RED_ADD_F32(dst,             acc.x);
        RED_ADD_F32(dst + PLANE,     acc.y);
        RED_ADD_F32(dst + 2 * PLANE, acc.z);
        RED_ADD_F32(dst + 3 * PLANE, acc.w);
    }
}

// ---------------------------------------------------------------------------
extern "C" void kernel_launch(void* const* d_in, const int* in_sizes, int n_in,
                              void* d_out, int out_size) {
    const float* x    = (const float*)d_in[0];
    const float* intr = (const float*)d_in[1];
    const float* pose = (const float*)d_in[2];
    float* out = (float*)d_out;

    // grid-stride: covers all OUT_F4 float4
    fp_zero<<<1184, 256>>>(out);

    // NCOL*32 = 737,280 threads = 2880 blocks x 256 (exact)
    fp_scatter<<<2880, 256>>>(x, intr, pose, out);
}